// round 16
// baseline (speedup 1.0000x reference)
#include <cuda_runtime.h>
#include <stdint.h>

#define V      10
#define L      45
#define NCOEF  14
#define RPB    128         // rows per block
#define TPB    512         // 4 threads per row
#define TSTR   100         // s_tile row stride in floats == M row size (exact image)

// smem: tile 51200 | pw 7920 | x 5632 | o 5120 = 69872 bytes
#define SMEM_BYTES 69872

__device__ __forceinline__ float warp_sum(float v) {
#pragma unroll
    for (int o = 16; o > 0; o >>= 1) v += __shfl_down_sync(0xffffffffu, v, o);
    return v;
}

__global__ __launch_bounds__(TPB, 3)
void decor_kernel(const float* __restrict__ x,
                  const float* __restrict__ log_d,
                  const float* __restrict__ params,
                  float* __restrict__ out_all,
                  int n_rows)
{
    extern __shared__ unsigned char smem_raw[];
    float*  s_tile = (float*)smem_raw;              // [RPB][100] M image
    float4* s_pw   = (float4*)(s_tile + RPB * TSTR);// [L*11] shifted windows
    float*  s_x    = (float*)(s_pw + L * 11);       // [RPB][11]
    float*  s_o    = s_x + RPB * 11;                // [RPB][10] out staging

    const int t = threadIdx.x;
    const int base = (int)blockIdx.x * RPB;
    const int nr = min(RPB, n_rows - base);
    const int r = t & (RPB - 1);
    const int q = t >> 7;               // quarter 0..3 (warp-uniform)

    // log_d: load to regs now, store at the end
    const int nld4 = (nr * V) / 4;
    float4 ld4 = make_float4(0.f, 0.f, 0.f, 0.f);
    if (t < nld4) ld4 = ((const float4*)(log_d + (size_t)base * V))[t];

    // ---- parallel init: warps 0-3 prefill constants; warps 4-15 build pw + stage x ----
    if (t < RPB) {
        if (t < nr) {
            float* row = s_tile + t * TSTR;
            const float4 Z4 = make_float4(0.f, 0.f, 0.f, 0.f);
            const float4 E4 = make_float4(1.f, 0.f, 0.f, 0.f);
            ((float4*)row)[0]  = E4;   // e0..3   (diag 0)
            ((float4*)row)[1]  = Z4;   // e4..7
            ((float4*)row)[3]  = Z4;   // e12..15
            ((float4*)row)[4]  = Z4;   // e16..19
            ((float4*)row)[6]  = Z4;   // e24..27
            ((float4*)row)[9]  = Z4;   // e36..39
            ((float4*)row)[11] = E4;   // e44..47 (diag 44)
            ((float4*)row)[14] = Z4;   // e56..59
            ((float2*)(row + 8))[0]  = make_float2(0.f, 0.f);
            ((float2*)(row + 28))[0] = make_float2(0.f, 0.f);
            ((float2*)(row + 34))[0] = make_float2(0.f, 0.f);
            ((float2*)(row + 48))[0] = make_float2(0.f, 0.f);
            ((float2*)(row + 68))[0] = make_float2(0.f, 0.f);
            ((float2*)(row + 78))[0] = make_float2(0.f, 0.f);
            row[23] = 0.f; row[67] = 0.f; row[89] = 0.f;
            row[11] = 1.f; row[22] = 1.f; row[33] = 1.f; row[55] = 1.f;
            row[66] = 1.f; row[77] = 1.f; row[88] = 1.f; row[99] = 1.f;
        }
    } else {
        const int u = t - RPB;          // 0..383
        for (int i = u; i < L * 11; i += TPB - RPB) {
            int l = i / 11, jj = i - l * 11;
            s_pw[i] = make_float4(params[jj * L + l],       params[(jj + 1) * L + l],
                                  params[(jj + 2) * L + l], params[(jj + 3) * L + l]);
        }
        for (int i = u; i < nr * V; i += TPB - RPB) {
            int rr = i / V, c = i - rr * V;
            s_x[rr * 11 + c] = x[(size_t)base * V + i];
        }
    }
    __syncthreads();   // #1

    // -------- spline + out, split by OUTPUT row i; lam scattered to final M slot --------
    if (r < nr) {
        float xr[V];
#pragma unroll
        for (int c = 0; c < V; c++) xr[c] = s_x[r * 11 + c];

        const float INV_D = 11.0f / 10.0f;   // knot spacing d = 10/11
        const float k6 = 1.0f / 6.0f;
        float* tr = s_tile + r * TSTR;       // my M row image
        float* so = s_o + r * V;

        float w0, w1, w2, w3;
        int   jj;

        // SAFE form: after clamp, xc+5 >= 0 exactly, so tt >= 0 and jj >= 0.
        // (R14 bug: fmaf(xc, INV_D, 5.5f) gives tt = -1.2e-7 at xc=-5 -> jj=-1 OOB.)
#define BASIS(jc)                                                             \
        do {                                                                  \
            float xc = fminf(fmaxf(xr[jc], -5.0f), 5.0f);                     \
            float tt = (xc + 5.0f) * INV_D;                                   \
            float fj = fmaxf(fminf(floorf(tt), 10.0f), 0.0f);                 \
            float u  = tt - fj;                                               \
            jj = (int)fj;                                                     \
            float um = 1.0f - u;                                              \
            float u2 = u * u, u3 = u2 * u;                                    \
            w0 = um * um * um * k6;                                           \
            w1 = (3.0f * u3 - 6.0f * u2 + 4.0f) * k6;                         \
            w2 = (-3.0f * u3 + 3.0f * u2 + 3.0f * u + 1.0f) * k6;             \
            w3 = u3 * k6;                                                     \
        } while (0)

#define LAM(ic, jc, acc)                                                      \
        do {                                                                  \
            const int l = ((ic) * ((ic) - 1)) / 2 + (jc);                     \
            float4 p = s_pw[l * 11 + jj];                                     \
            float lv = w0 * p.x + w1 * p.y + w2 * p.z + w3 * p.w;             \
            tr[10 * (ic) + (jc)] = lv;                                        \
            acc = fmaf(lv, xr[jc], acc);                                      \
        } while (0)

        switch (q) {
            case 0: {   // i = 9 : 9 bases, 9 lams
                float a9 = xr[9];
                BASIS(0); LAM(9, 0, a9);
                BASIS(1); LAM(9, 1, a9);
                BASIS(2); LAM(9, 2, a9);
                BASIS(3); LAM(9, 3, a9);
                BASIS(4); LAM(9, 4, a9);
                BASIS(5); LAM(9, 5, a9);
                BASIS(6); LAM(9, 6, a9);
                BASIS(7); LAM(9, 7, a9);
                BASIS(8); LAM(9, 8, a9);
                so[9] = a9;
                break;
            }
            case 1: {   // i in {8, 2}: 8 bases, 10 lams
                float a8 = xr[8], a2 = xr[2];
                BASIS(0); LAM(8, 0, a8); LAM(2, 0, a2);
                BASIS(1); LAM(8, 1, a8); LAM(2, 1, a2);
                BASIS(2); LAM(8, 2, a8);
                BASIS(3); LAM(8, 3, a8);
                BASIS(4); LAM(8, 4, a8);
                BASIS(5); LAM(8, 5, a8);
                BASIS(6); LAM(8, 6, a8);
                BASIS(7); LAM(8, 7, a8);
                so[8] = a8; so[2] = a2;
                break;
            }
            case 2: {   // i in {7, 4, 1}: 7 bases, 12 lams
                float a7 = xr[7], a4 = xr[4], a1 = xr[1];
                BASIS(0); LAM(7, 0, a7); LAM(4, 0, a4); LAM(1, 0, a1);
                BASIS(1); LAM(7, 1, a7); LAM(4, 1, a4);
                BASIS(2); LAM(7, 2, a7); LAM(4, 2, a4);
                BASIS(3); LAM(7, 3, a7); LAM(4, 3, a4);
                BASIS(4); LAM(7, 4, a7);
                BASIS(5); LAM(7, 5, a7);
                BASIS(6); LAM(7, 6, a7);
                so[7] = a7; so[4] = a4; so[1] = a1;
                break;
            }
            default: {  // i in {6, 5, 3, 0}: 6 bases, 14 lams
                float a6 = xr[6], a5 = xr[5], a3 = xr[3];
                BASIS(0); LAM(6, 0, a6); LAM(5, 0, a5); LAM(3, 0, a3);
                BASIS(1); LAM(6, 1, a6); LAM(5, 1, a5); LAM(3, 1, a3);
                BASIS(2); LAM(6, 2, a6); LAM(5, 2, a5); LAM(3, 2, a3);
                BASIS(3); LAM(6, 3, a6); LAM(5, 3, a5);
                BASIS(4); LAM(6, 4, a6); LAM(5, 4, a5);
                BASIS(5); LAM(6, 5, a6);
                so[6] = a6; so[5] = a5; so[3] = a3; so[0] = xr[0];
                break;
            }
        }
#undef BASIS
#undef LAM
    }
    __syncthreads();   // #2  (tile and s_o complete)

    // -------- M copy-out: tile IS the M slab image; pure LDS.128 -> STG.128 --------
    {
        float4* Mb4 = (float4*)(out_all + (size_t)n_rows * V) + (size_t)base * 25;
        const float4* tile4 = (const float4*)s_tile;
        const int nq = nr * 25;             // 3200 when full = 6*512 + 128
        if (nr == RPB) {
#pragma unroll
            for (int k = 0; k < 6; k++) Mb4[t + TPB * k] = tile4[t + TPB * k];
            if (t < 128) Mb4[t + TPB * 6] = tile4[t + TPB * 6];
        } else {
            for (int g = t; g < nq; g += TPB) Mb4[g] = tile4[g];
        }
    }

    // -------- out copy-out: s_o is exactly output layout --------
    {
        float* dst = out_all + (size_t)base * V;
        const int nfl = nr * V;
        const int n4 = nfl / 4;
        const float4* s4 = (const float4*)s_o;
        for (int g = t; g < n4; g += TPB) ((float4*)dst)[g] = s4[g];
        for (int g = n4 * 4 + t; g < nfl; g += TPB) dst[g] = s_o[g];
    }

    // -------- log_d store --------
    {
        float* ldo = out_all + (size_t)n_rows * (V + V * V) + (size_t)base * V;
        if (t < nld4) ((float4*)ldo)[t] = ld4;
        for (int g2 = nld4 * 4 + t; g2 < nr * V; g2 += TPB)
            ldo[g2] = log_d[(size_t)base * V + g2];
    }

    // -------- penalties: block 0 only, straight from params (L1-hot) --------
    if (blockIdx.x == 0) {
        float par = 0.f, fir = 0.f, sec = 0.f;
        for (int i = t; i < NCOEF * L; i += TPB) { float v = params[i]; par += v * v; }
        for (int i = t; i < (NCOEF - 1) * L; i += TPB) {
            float d = params[i + L] - params[i]; fir += d * d;
        }
        for (int i = t; i < (NCOEF - 2) * L; i += TPB) {
            float d = params[i + 2 * L] - 2.f * params[i + L] + params[i];
            sec += d * d;
        }
        par = warp_sum(par); fir = warp_sum(fir); sec = warp_sum(sec);
        int lane = t & 31, w = t >> 5;
        __syncthreads();                       // s_x reads finished at barrier #2
        if (lane == 0) { s_x[w] = sec; s_x[16 + w] = fir; s_x[32 + w] = par; }
        __syncthreads();
        if (w == 0) {
            float s = (lane < 16) ? s_x[lane] : 0.f;
            float f = (lane < 16) ? s_x[16 + lane] : 0.f;
            float p = (lane < 16) ? s_x[32 + lane] : 0.f;
            s = warp_sum(s); f = warp_sum(f); p = warp_sum(p);
            if (lane == 0) {
                float* tail = out_all + (size_t)n_rows * (V + V * V + V);
                tail[0] = s; tail[1] = f; tail[2] = p;
            }
        }
    }
}

extern "C" void kernel_launch(void* const* d_in, const int* in_sizes, int n_in,
                              void* d_out, int out_size)
{
    const float* x      = (const float*)d_in[0];
    const float* log_d  = (const float*)d_in[1];
    const float* params = (const float*)d_in[2];
    float* out_all = (float*)d_out;

    cudaFuncSetAttribute((const void*)decor_kernel,
                         cudaFuncAttributeMaxDynamicSharedMemorySize, SMEM_BYTES);

    int n_rows = in_sizes[0] / V;
    int main_blocks = (n_rows + RPB - 1) / RPB;
    decor_kernel<<<main_blocks, TPB, SMEM_BYTES>>>(x, log_d, params, out_all, n_rows);
}

// round 17
// speedup vs baseline: 1.0823x; 1.0823x over previous
#include <cuda_runtime.h>
#include <stdint.h>

#define V      10
#define L      45
#define NCOEF  14
#define RPB    128         // rows per block
#define TPB    512         // 4 threads per row
#define CSTR   129         // s_lam column stride (RPB+1, odd)
#define NSLOT  48          // slots 0..44 lam, 46 -> 1.0, 47 -> 0.0

// smem bytes/offsets (all float4 regions 16B-aligned):
// pw 0..7920 | o 7920..13040 | x 13040..18672 | lam 18672..43440 | map 43440..43640
#define SMEM_BYTES 43640

__device__ __forceinline__ float warp_sum(float v) {
#pragma unroll
    for (int o = 16; o > 0; o >>= 1) v += __shfl_down_sync(0xffffffffu, v, o);
    return v;
}

__global__ __launch_bounds__(TPB, 4)   // cap regs at 32 -> 4 blocks/SM -> single wave
void decor_kernel(const float* __restrict__ x,
                  const float* __restrict__ log_d,
                  const float* __restrict__ params,
                  float* __restrict__ out_all,
                  int n_rows)
{
    extern __shared__ unsigned char smem_raw[];
    float4* s_pw  = (float4*)smem_raw;              // [L*11] shifted windows
    float*  s_o   = (float*)(s_pw + L * 11);        // [RPB*10] out staging
    float*  s_x   = s_o + RPB * V;                  // [RPB*11]
    float*  s_lam = s_x + RPB * 11;                 // [NSLOT][CSTR] col-major
    uint2*  s_map = (uint2*)(s_lam + NSLOT * CSTR); // [25] packed offsets

    const int t = threadIdx.x;
    const int base = (int)blockIdx.x * RPB;
    const int nr = min(RPB, n_rows - base);
    const int r = t & (RPB - 1);
    const int q = t >> 7;               // quarter 0..3 (warp-uniform)

    // log_d: load to regs now, store at the end
    const int nld4 = (nr * V) / 4;
    float4 ld4 = make_float4(0.f, 0.f, 0.f, 0.f);
    if (t < nld4) ld4 = ((const float4*)(log_d + (size_t)base * V))[t];

    // packed M map: col -> 4 premultiplied lam offsets (m*CSTR), 16-bit fields
    if (t < 25) {
        unsigned lo = 0, hi = 0;
#pragma unroll
        for (int s = 0; s < 4; s++) {
            int ij = 4 * t + s;
            int i = ij / 10, j = ij - 10 * i;
            int m = (i == j) ? 46 : ((i > j) ? (i * (i - 1)) / 2 + j : 47);
            unsigned mo = (unsigned)(m * CSTR);
            if (s < 2) lo |= mo << (16 * s);
            else       hi |= mo << (16 * (s - 2));
        }
        s_map[t] = make_uint2(lo, hi);
    }

    // window table straight from global params (L1/L2-hot, 2.5KB)
    for (int i = t; i < L * 11; i += TPB) {
        int l = i / 11, jj = i - l * 11;
        s_pw[i] = make_float4(params[jj * L + l],       params[(jj + 1) * L + l],
                              params[(jj + 2) * L + l], params[(jj + 3) * L + l]);
    }

    // stage x (coalesced in, padded out)
    for (int i = t; i < nr * V; i += TPB) {
        int rr = i / V, c = i - rr * V;
        s_x[rr * 11 + c] = x[(size_t)base * V + i];
    }
    __syncthreads();   // #1

    // -------- spline + out, split by OUTPUT row i; lam kept in regs for out --------
    if (r < nr) {
        float xr[V];
#pragma unroll
        for (int c = 0; c < V; c++) xr[c] = s_x[r * 11 + c];

        const float INV_D = 11.0f / 10.0f;   // knot spacing d = 10/11
        const float k6 = 1.0f / 6.0f;
        float* lr = s_lam + r;               // slot m -> lr[m*CSTR]
        float* so = s_o + r * V;

        float w0, w1, w2, w3;
        int   jj;

        // SAFE basis form: after clamp, xc+5 >= 0 exactly -> tt >= 0 -> jj >= 0.
#define BASIS(jc)                                                             \
        do {                                                                  \
            float xc = fminf(fmaxf(xr[jc], -5.0f), 5.0f);                     \
            float tt = (xc + 5.0f) * INV_D;                                   \
            float fj = fminf(floorf(tt), 10.0f);                              \
            float u  = tt - fj;                                               \
            jj = (int)fj;                                                     \
            float um = 1.0f - u;                                              \
            float u2 = u * u, u3 = u2 * u;                                    \
            w0 = um * um * um * k6;                                           \
            w1 = (3.0f * u3 - 6.0f * u2 + 4.0f) * k6;                         \
            w2 = (-3.0f * u3 + 3.0f * u2 + 3.0f * u + 1.0f) * k6;             \
            w3 = u3 * k6;                                                     \
        } while (0)

#define LAM(ic, jc, acc)                                                      \
        do {                                                                  \
            const int l = ((ic) * ((ic) - 1)) / 2 + (jc);                     \
            float4 p = s_pw[l * 11 + jj];                                     \
            float lv = w0 * p.x + w1 * p.y + w2 * p.z + w3 * p.w;             \
            lr[l * CSTR] = lv;                                                \
            acc = fmaf(lv, xr[jc], acc);                                      \
        } while (0)

        switch (q) {
            case 0: {   // i in {9, 2}: 11 lams, 9 bases
                float a9 = xr[9], a2 = xr[2];
                BASIS(0); LAM(9, 0, a9); LAM(2, 0, a2);
                BASIS(1); LAM(9, 1, a9); LAM(2, 1, a2);
                BASIS(2); LAM(9, 2, a9);
                BASIS(3); LAM(9, 3, a9);
                BASIS(4); LAM(9, 4, a9);
                BASIS(5); LAM(9, 5, a9);
                BASIS(6); LAM(9, 6, a9);
                BASIS(7); LAM(9, 7, a9);
                BASIS(8); LAM(9, 8, a9);
                so[9] = a9; so[2] = a2;
                break;
            }
            case 1: {   // i in {8, 3}: 11 lams, 8 bases
                float a8 = xr[8], a3 = xr[3];
                BASIS(0); LAM(8, 0, a8); LAM(3, 0, a3);
                BASIS(1); LAM(8, 1, a8); LAM(3, 1, a3);
                BASIS(2); LAM(8, 2, a8); LAM(3, 2, a3);
                BASIS(3); LAM(8, 3, a8);
                BASIS(4); LAM(8, 4, a8);
                BASIS(5); LAM(8, 5, a8);
                BASIS(6); LAM(8, 6, a8);
                BASIS(7); LAM(8, 7, a8);
                so[8] = a8; so[3] = a3;
                break;
            }
            case 2: {   // i in {7, 4, 1}: 12 lams, 7 bases
                float a7 = xr[7], a4 = xr[4], a1 = xr[1];
                BASIS(0); LAM(7, 0, a7); LAM(4, 0, a4); LAM(1, 0, a1);
                BASIS(1); LAM(7, 1, a7); LAM(4, 1, a4);
                BASIS(2); LAM(7, 2, a7); LAM(4, 2, a4);
                BASIS(3); LAM(7, 3, a7); LAM(4, 3, a4);
                BASIS(4); LAM(7, 4, a7);
                BASIS(5); LAM(7, 5, a7);
                BASIS(6); LAM(7, 6, a7);
                so[7] = a7; so[4] = a4; so[1] = a1;
                break;
            }
            default: {  // i in {6, 5, 0}: 11 lams, 6 bases (+ constants)
                lr[46 * CSTR] = 1.0f; lr[47 * CSTR] = 0.0f;
                float a6 = xr[6], a5 = xr[5];
                BASIS(0); LAM(6, 0, a6); LAM(5, 0, a5);
                BASIS(1); LAM(6, 1, a6); LAM(5, 1, a5);
                BASIS(2); LAM(6, 2, a6); LAM(5, 2, a5);
                BASIS(3); LAM(6, 3, a6); LAM(5, 3, a5);
                BASIS(4); LAM(6, 4, a6); LAM(5, 4, a5);
                BASIS(5); LAM(6, 5, a6);
                so[6] = a6; so[5] = a5; so[0] = xr[0];
                break;
            }
        }
#undef BASIS
#undef LAM
    }
    __syncthreads();   // #2  (s_lam and s_o both complete)

    // -------- M writer: premultiplied map, column-major lam, unrolled fast path --------
    {
        float4* Mb4 = (float4*)(out_all + (size_t)n_rows * V) + (size_t)base * 25;
        if (nr == RPB) {
            // nq = 3200 = 6*512 + 128 ; step: 512 = 20*25 + 12
            int row = t / 25, col = t - (t / 25) * 25;
#pragma unroll
            for (int k = 0; k < 6; k++) {
                uint2 mp = s_map[col];
                const float* lrb = s_lam + row;
                float4 v;
                v.x = lrb[mp.x & 0xffffu];
                v.y = lrb[mp.x >> 16];
                v.z = lrb[mp.y & 0xffffu];
                v.w = lrb[mp.y >> 16];
                Mb4[t + TPB * k] = v;
                row += 20; col += 12;
                if (col >= 25) { col -= 25; row += 1; }
            }
            if (t < 128) {
                uint2 mp = s_map[col];
                const float* lrb = s_lam + row;
                float4 v;
                v.x = lrb[mp.x & 0xffffu];
                v.y = lrb[mp.x >> 16];
                v.z = lrb[mp.y & 0xffffu];
                v.w = lrb[mp.y >> 16];
                Mb4[t + TPB * 6] = v;
            }
        } else {
            const int nq = nr * 25;
            int g = t, row = t / 25, col = t - (t / 25) * 25;
            while (g < nq) {
                uint2 mp = s_map[col];
                const float* lrb = s_lam + row;
                float4 v;
                v.x = lrb[mp.x & 0xffffu];
                v.y = lrb[mp.x >> 16];
                v.z = lrb[mp.y & 0xffffu];
                v.w = lrb[mp.y >> 16];
                Mb4[g] = v;
                g += TPB; row += 20; col += 12;
                if (col >= 25) { col -= 25; row += 1; }
            }
        }
    }

    // -------- out copy-out: s_o is exactly output layout --------
    {
        float* dst = out_all + (size_t)base * V;
        const int nfl = nr * V;
        const int n4 = nfl / 4;
        const float4* s4 = (const float4*)s_o;
        for (int g = t; g < n4; g += TPB) ((float4*)dst)[g] = s4[g];
        for (int g = n4 * 4 + t; g < nfl; g += TPB) dst[g] = s_o[g];
    }

    // -------- log_d store --------
    {
        float* ldo = out_all + (size_t)n_rows * (V + V * V) + (size_t)base * V;
        if (t < nld4) ((float4*)ldo)[t] = ld4;
        for (int g2 = nld4 * 4 + t; g2 < nr * V; g2 += TPB)
            ldo[g2] = log_d[(size_t)base * V + g2];
    }

    // -------- penalties: block 0 only, straight from params (L1-hot) --------
    if (blockIdx.x == 0) {
        float par = 0.f, fir = 0.f, sec = 0.f;
        for (int i = t; i < NCOEF * L; i += TPB) { float v = params[i]; par += v * v; }
        for (int i = t; i < (NCOEF - 1) * L; i += TPB) {
            float d = params[i + L] - params[i]; fir += d * d;
        }
        for (int i = t; i < (NCOEF - 2) * L; i += TPB) {
            float d = params[i + 2 * L] - 2.f * params[i + L] + params[i];
            sec += d * d;
        }
        par = warp_sum(par); fir = warp_sum(fir); sec = warp_sum(sec);
        int lane = t & 31, w = t >> 5;
        __syncthreads();                       // s_x reads finished at barrier #2
        if (lane == 0) { s_x[w] = sec; s_x[16 + w] = fir; s_x[32 + w] = par; }
        __syncthreads();
        if (w == 0) {
            float s = (lane < 16) ? s_x[lane] : 0.f;
            float f = (lane < 16) ? s_x[16 + lane] : 0.f;
            float p = (lane < 16) ? s_x[32 + lane] : 0.f;
            s = warp_sum(s); f = warp_sum(f); p = warp_sum(p);
            if (lane == 0) {
                float* tail = out_all + (size_t)n_rows * (V + V * V + V);
                tail[0] = s; tail[1] = f; tail[2] = p;
            }
        }
    }
}

extern "C" void kernel_launch(void* const* d_in, const int* in_sizes, int n_in,
                              void* d_out, int out_size)
{
    const float* x      = (const float*)d_in[0];
    const float* log_d  = (const float*)d_in[1];
    const float* params = (const float*)d_in[2];
    float* out_all = (float*)d_out;

    cudaFuncSetAttribute((const void*)decor_kernel,
                         cudaFuncAttributeMaxDynamicSharedMemorySize, SMEM_BYTES);

    int n_rows = in_sizes[0] / V;
    int main_blocks = (n_rows + RPB - 1) / RPB;
    decor_kernel<<<main_blocks, TPB, SMEM_BYTES>>>(x, log_d, params, out_all, n_rows);
}